// round 16
// baseline (speedup 1.0000x reference)
#include <cuda_runtime.h>
#include <cuda_fp16.h>
#include <cstdint>

#define K_B 4
#define K_S 2048
#define K_D 1024
#define K_H 16
#define K_DH 64
#define K_ROWS (K_B * K_S)   // 8192

// Half-precision scratch (device globals: allocation-free per harness rules)
__device__ __half g_Xq[K_ROWS * K_D];
__device__ __half g_Xk[K_ROWS * K_D];
__device__ __half g_Xv[K_ROWS * K_D];
__device__ __half g_hWq[K_D * K_D];
__device__ __half g_hWk[K_D * K_D];
__device__ __half g_hWv[K_D * K_D];
__device__ __half g_hWo[K_D * K_D];
__device__ __half g_Qh[K_ROWS * K_D];
__device__ __half g_Kh[K_ROWS * K_D];
__device__ __half g_Vh[K_ROWS * K_D];
__device__ __half g_Ch[K_ROWS * K_D];

// ---------------------------------------------------------------------------
// helpers
// ---------------------------------------------------------------------------
__device__ __forceinline__ unsigned h2u(__half2 h) {
    return *reinterpret_cast<unsigned*>(&h);
}

__device__ __forceinline__ float ex2f(float x) {
    float y;
    asm("ex2.approx.f32 %0, %1;" : "=f"(y) : "f"(x));
    return y;
}

// pack two f32 into f16x2 (lo = flo, hi = fhi) then exp2 both halves in one MUFU
__device__ __forceinline__ unsigned ex2_h2(float flo, float fhi) {
    unsigned r;
    asm("{\n\t.reg .b32 t;\n\t"
        "cvt.rn.f16x2.f32 t, %2, %1;\n\t"
        "ex2.approx.f16x2 %0, t;\n\t}"
        : "=r"(r) : "f"(flo), "f"(fhi));
    return r;
}

__device__ __forceinline__ void mma_f16(float* d, const uint4 a, unsigned b0, unsigned b1) {
    asm volatile(
        "mma.sync.aligned.m16n8k16.row.col.f32.f16.f16.f32 "
        "{%0,%1,%2,%3}, {%4,%5,%6,%7}, {%8,%9}, {%0,%1,%2,%3};\n"
        : "+f"(d[0]), "+f"(d[1]), "+f"(d[2]), "+f"(d[3])
        : "r"(a.x), "r"(a.y), "r"(a.z), "r"(a.w), "r"(b0), "r"(b1));
}

__device__ __forceinline__ void ldsm_x4(uint4& d, unsigned addr) {
    asm volatile("ldmatrix.sync.aligned.m8n8.x4.shared.b16 {%0,%1,%2,%3}, [%4];"
        : "=r"(d.x), "=r"(d.y), "=r"(d.z), "=r"(d.w) : "r"(addr));
}

__device__ __forceinline__ void ldsm_x4_t(uint4& d, unsigned addr) {
    asm volatile("ldmatrix.sync.aligned.m8n8.x4.trans.shared.b16 {%0,%1,%2,%3}, [%4];"
        : "=r"(d.x), "=r"(d.y), "=r"(d.z), "=r"(d.w) : "r"(addr));
}

__device__ __forceinline__ void cp16(unsigned dst, const void* src) {
    asm volatile("cp.async.cg.shared.global [%0], [%1], 16;\n" :: "r"(dst), "l"(src));
}
#define CP_COMMIT() asm volatile("cp.async.commit_group;\n" ::: "memory")
#define CP_WAIT0()  asm volatile("cp.async.wait_group 0;\n" ::: "memory")
#define CP_WAIT1()  asm volatile("cp.async.wait_group 1;\n" ::: "memory")
#define CP_WAIT2()  asm volatile("cp.async.wait_group 2;\n" ::: "memory")

#define ONES_F16X2 0x3C003C00u   // (1.0h, 1.0h)

// ---------------------------------------------------------------------------
// Conversion kernel: f32 -> f16 for 3 activations + 4 weight matrices
// ---------------------------------------------------------------------------
__global__ __launch_bounds__(256) void cvt_all(
    const float* s0, const float* s1, const float* s2, const float* s3,
    const float* s4, const float* s5, const float* s6,
    __half* d0, __half* d1, __half* d2, __half* d3,
    __half* d4, __half* d5, __half* d6)
{
    const float* ss[7] = {s0, s1, s2, s3, s4, s5, s6};
    __half* dd[7] = {d0, d1, d2, d3, d4, d5, d6};
    int t = blockIdx.y;
    int n4 = (t < 3) ? (K_ROWS * K_D / 4) : (K_D * K_D / 4);
    const float4* src = (const float4*)ss[t];
    uint2* dst = (uint2*)dd[t];
    for (int i = blockIdx.x * 256 + threadIdx.x; i < n4; i += gridDim.x * 256) {
        float4 v = src[i];
        uint2 w;
        w.x = h2u(__floats2half2_rn(v.x, v.y));
        w.y = h2u(__floats2half2_rn(v.z, v.w));
        dst[i] = w;
    }
}

// ---------------------------------------------------------------------------
// GEMM (unchanged, best measured): out = x @ W^T + bias.
// BM=BN=128, BK=64, 256 threads (8 warps), warp tile 32x64.
// 3-stage cp.async pipeline, ONE __syncthreads per 64-wide k-iter.
// Dynamic smem: 3 * (18432 A + 18432 B) = 110592 B. 2 CTAs/SM.
// ---------------------------------------------------------------------------
extern __shared__ unsigned char smem_raw[];

#define G_STRIDE 144u
#define G_TILE   18432u
#define G_STAGE  36864u

template <typename OutT>
__global__ __launch_bounds__(256, 2) void gemm_tc(
    const __half* __restrict__ x0, const __half* __restrict__ x1, const __half* __restrict__ x2,
    const __half* __restrict__ w0, const __half* __restrict__ w1, const __half* __restrict__ w2,
    const float* __restrict__ b0,  const float* __restrict__ b1,  const float* __restrict__ b2,
    OutT* __restrict__ o0, OutT* __restrict__ o1, OutT* __restrict__ o2)
{
    const int z = blockIdx.z;
    const __half* x = (z == 0) ? x0 : (z == 1) ? x1 : x2;
    const __half* W = (z == 0) ? w0 : (z == 1) ? w1 : w2;
    const float* bias = (z == 0) ? b0 : (z == 1) ? b1 : b2;
    OutT* out = (z == 0) ? o0 : (z == 1) ? o1 : o2;

    const int tid  = threadIdx.x;
    const int lane = tid & 31;
    const int warp = tid >> 5;
    const int wm = warp >> 1;
    const int wn = warp & 1;
    const int rowBase = blockIdx.y * 128;
    const int colBase = blockIdx.x * 128;

    const unsigned sb = (unsigned)__cvta_generic_to_shared(smem_raw);
    const int u = lane >> 3, j = lane & 7;
    const int a_row = wm * 32 + (u & 1) * 8 + j;
    const int a_kx  = (u >> 1) * 16;
    const int b_row = wn * 64 + (u >> 1) * 8 + j;
    const int b_kx  = (u & 1) * 16;

    auto stage = [&](int t, int s) {
        const unsigned ab = sb + (unsigned)s * G_STAGE;
        const unsigned bb = ab + G_TILE;
        const int k0 = t * 64;
        #pragma unroll
        for (int i = 0; i < 4; i++) {
            int ca = tid + i * 256;
            int r = ca >> 3, c = ca & 7;
            cp16(ab + (unsigned)(r * G_STRIDE + c * 16),
                 x + (size_t)(rowBase + r) * K_D + k0 + c * 8);
            cp16(bb + (unsigned)(r * G_STRIDE + c * 16),
                 W + (size_t)(colBase + r) * K_D + k0 + c * 8);
        }
        CP_COMMIT();
    };

    float acc[2][8][4];
    #pragma unroll
    for (int mi = 0; mi < 2; mi++)
        #pragma unroll
        for (int ni = 0; ni < 8; ni++)
            #pragma unroll
            for (int v = 0; v < 4; v++) acc[mi][ni][v] = 0.f;

    const int NT = K_D / 64;
    stage(0, 0);
    stage(1, 1);

    for (int it = 0; it < NT; it++) {
        const int buf = it % 3;
        if (it == NT - 1) { CP_WAIT0(); } else { CP_WAIT1(); }
        __syncthreads();
        if (it + 2 < NT) stage(it + 2, (it + 2) % 3);

        const unsigned ab = sb + (unsigned)buf * G_STAGE;
        const unsigned bb_ = ab + G_TILE;
        #pragma unroll
        for (int kt = 0; kt < 4; kt++) {
            uint4 afr[2];
            #pragma unroll
            for (int mi = 0; mi < 2; mi++)
                ldsm_x4(afr[mi], ab + (unsigned)((a_row + mi * 16) * G_STRIDE + kt * 32 + a_kx));
            #pragma unroll
            for (int np = 0; np < 4; np++) {
                uint4 bb;
                ldsm_x4(bb, bb_ + (unsigned)((b_row + np * 16) * G_STRIDE + kt * 32 + b_kx));
                #pragma unroll
                for (int mi = 0; mi < 2; mi++) {
                    mma_f16(acc[mi][2 * np],     afr[mi], bb.x, bb.y);
                    mma_f16(acc[mi][2 * np + 1], afr[mi], bb.z, bb.w);
                }
            }
        }
    }

    #pragma unroll
    for (int mi = 0; mi < 2; mi++) {
        int row0 = rowBase + (wm * 2 + mi) * 16 + (lane >> 2);
        #pragma unroll
        for (int ni = 0; ni < 8; ni++) {
            int col = colBase + (wn * 8 + ni) * 8 + (lane & 3) * 2;
            float bb0 = __ldg(&bias[col]);
            float bb1 = __ldg(&bias[col + 1]);
            float c00 = acc[mi][ni][0] + bb0, c01 = acc[mi][ni][1] + bb1;
            float c10 = acc[mi][ni][2] + bb0, c11 = acc[mi][ni][3] + bb1;
            if constexpr (sizeof(OutT) == 2) {
                *(__half2*)&out[(size_t)row0 * K_D + col] = __floats2half2_rn(c00, c01);
                *(__half2*)&out[(size_t)(row0 + 8) * K_D + col] = __floats2half2_rn(c10, c11);
            } else {
                *(float2*)&out[(size_t)row0 * K_D + col] = make_float2(c00, c01);
                *(float2*)&out[(size_t)(row0 + 8) * K_D + col] = make_float2(c10, c11);
            }
        }
    }
}

// ---------------------------------------------------------------------------
// Flash attention: Br=64, 128 threads (4 warps, warp tile 16x64), 3 CTAs/SM.
// Q fragments hoisted into registers (loaded once). Bc=64, 3-stage cp.async,
// half2-exp softmax, row-sum via MMA-with-ones, alpha-skip rescale.
// Grid: (B*H, S/64) = (64, 32) = 2048 CTAs.
// Dynamic smem: Q 9216 + 3*(K 9216 + V 9216) = 64512 B. 3 CTAs/SM = 193.5KB.
// ---------------------------------------------------------------------------
__global__ __launch_bounds__(128, 3) void flash_tc(
    const __half* __restrict__ Q, const __half* __restrict__ K,
    const __half* __restrict__ V, __half* __restrict__ O)
{
    const unsigned qs_base = (unsigned)__cvta_generic_to_shared(smem_raw);

    const int tid  = threadIdx.x;
    const int lane = tid & 31;
    const int warp = tid >> 5;   // 0..3

    const int bh = blockIdx.x;
    const int b = bh / K_H, h = bh % K_H;
    const int qbase = blockIdx.y * 64;
    const size_t base = (size_t)b * K_S * K_D + (size_t)h * K_DH;
    const float cl2 = 0.18033688f;   // (1/sqrt(64)) * log2(e)

    const int u = lane >> 3, j = lane & 7;
    const int q_row = warp * 16 + (u & 1) * 8 + j;
    const int q_kx  = (u >> 1) * 16;
    const int k_row = (u >> 1) * 8 + j;
    const int k_kx  = (u & 1) * 16;
    const int v_row = (u & 1) * 8 + j;
    const int v_dx  = (u >> 1) * 16;

    // K/V staging: 64 rows x 8 chunks = 512 chunks per tensor, 4/thread each
    auto stage_kv = [&](int t, int s) {
        const unsigned kb = qs_base + 9216u + (unsigned)s * 18432u;
        const unsigned vb = kb + 9216u;
        const int r0 = t * 64;
        #pragma unroll
        for (int i = 0; i < 4; i++) {
            int ca = tid + i * 128;
            int r = ca >> 3, ch = ca & 7;
            cp16(kb + (unsigned)(r * 144 + ch * 16),
                 K + base + (size_t)(r0 + r) * K_D + ch * 8);
            cp16(vb + (unsigned)(r * 144 + ch * 16),
                 V + base + (size_t)(r0 + r) * K_D + ch * 8);
        }
        CP_COMMIT();
    };

    // prologue: stage Q (64 rows x 8 chunks = 512, 4/thread) as its own group
    #pragma unroll
    for (int i = 0; i < 4; i++) {
        int c = tid + i * 128;
        int r = c >> 3, ch = c & 7;
        cp16(qs_base + (unsigned)(r * 144 + ch * 16),
             Q + base + (size_t)(qbase + r) * K_D + ch * 8);
    }
    CP_COMMIT();
    stage_kv(0, 0);
    stage_kv(1, 1);

    // wait for Q group (2 groups may remain in flight), then hoist Q to regs
    CP_WAIT2();
    __syncthreads();
    uint4 qf[4];
    #pragma unroll
    for (int kt = 0; kt < 4; kt++)
        ldsm_x4(qf[kt], qs_base + (unsigned)(q_row * 144 + kt * 32 + q_kx));

    float accO[8][4];
    #pragma unroll
    for (int ni = 0; ni < 8; ni++)
        #pragma unroll
        for (int v = 0; v < 4; v++) accO[ni][v] = 0.f;

    float m0 = -1e30f, m1 = -1e30f, l0 = 0.f, l1 = 0.f;

    const int NT = K_S / 64;   // 32 kv tiles

    for (int it = 0; it < NT; it++) {
        const int buf = it % 3;
        if (it == NT - 1) { CP_WAIT0(); } else { CP_WAIT1(); }
        __syncthreads();
        if (it + 2 < NT) stage_kv(it + 2, (it + 2) % 3);

        const unsigned ks = qs_base + 9216u + (unsigned)buf * 18432u;
        const unsigned vs = ks + 9216u;

        // ---- S = Q K^T : warp tile 16q x 64kv (Q from registers) ----
        float accS[8][4];
        #pragma unroll
        for (int ni = 0; ni < 8; ni++)
            #pragma unroll
            for (int v = 0; v < 4; v++) accS[ni][v] = 0.f;

        #pragma unroll
        for (int kt = 0; kt < 4; kt++) {
            #pragma unroll
            for (int np = 0; np < 4; np++) {
                uint4 bb;
                ldsm_x4(bb, ks + (unsigned)((k_row + np * 16) * 144 + kt * 32 + k_kx));
                mma_f16(accS[2 * np],     qf[kt], bb.x, bb.y);
                mma_f16(accS[2 * np + 1], qf[kt], bb.z, bb.w);
            }
        }

        // ---- online softmax in exp2 domain (rows lane>>2, +8; quad-local) ----
        float mx0 = -1e30f, mx1 = -1e30f;
        #pragma unroll
        for (int ni = 0; ni < 8; ni++) {
            mx0 = fmaxf(mx0, fmaxf(accS[ni][0], accS[ni][1]));
            mx1 = fmaxf(mx1, fmaxf(accS[ni][2], accS[ni][3]));
        }
        mx0 = fmaxf(mx0, __shfl_xor_sync(0xffffffffu, mx0, 1));
        mx0 = fmaxf(mx0, __shfl_xor_sync(0xffffffffu, mx0, 2));
        mx1 = fmaxf(mx1, __shfl_xor_sync(0xffffffffu, mx1, 1));
        mx1 = fmaxf(mx1, __shfl_xor_sync(0xffffffffu, mx1, 2));

        float mn0 = fmaxf(m0, mx0);
        float mn1 = fmaxf(m1, mx1);
        bool need = (mn0 > m0) || (mn1 > m1);
        if (__any_sync(0xffffffffu, need)) {
            float alpha0 = ex2f((m0 - mn0) * cl2);
            float alpha1 = ex2f((m1 - mn1) * cl2);
            #pragma unroll
            for (int ni = 0; ni < 8; ni++) {
                accO[ni][0] *= alpha0; accO[ni][1] *= alpha0;
                accO[ni][2] *= alpha1; accO[ni][3] *= alpha1;
            }
            l0 *= alpha0;
            l1 *= alpha1;
            m0 = mn0; m1 = mn1;
        }
        float mc0 = m0 * cl2, mc1 = m1 * cl2;

        unsigned uP[8][2];
        #pragma unroll
        for (int ni = 0; ni < 8; ni++) {
            uP[ni][0] = ex2_h2(fmaf(accS[ni][0], cl2, -mc0),
                               fmaf(accS[ni][1], cl2, -mc0));
            uP[ni][1] = ex2_h2(fmaf(accS[ni][2], cl2, -mc1),
                               fmaf(accS[ni][3], cl2, -mc1));
        }

        // ---- O += P @ V, plus row-sum via MMA with ones ----
        float accL[4] = {0.f, 0.f, 0.f, 0.f};
        #pragma unroll
        for (int kt = 0; kt < 4; kt++) {
            uint4 aP;
            aP.x = uP[2 * kt][0];
            aP.y = uP[2 * kt][1];
            aP.z = uP[2 * kt + 1][0];
            aP.w = uP[2 * kt + 1][1];
            mma_f16(accL, aP, ONES_F16X2, ONES_F16X2);
            #pragma unroll
            for (int np = 0; np < 4; np++) {
                uint4 bb;
                ldsm_x4_t(bb, vs + (unsigned)((kt * 16 + v_row) * 144 + np * 32 + v_dx));
                mma_f16(accO[2 * np],     aP, bb.x, bb.y);
                mma_f16(accO[2 * np + 1], aP, bb.z, bb.w);
            }
        }
        l0 += accL[0];
        l1 += accL[2];
    }

    // Epilogue: normalize and write half context
    float inv0 = 1.0f / l0;
    float inv1 = 1.0f / l1;
    int row0 = qbase + warp * 16 + (lane >> 2);
    #pragma unroll
    for (int ni = 0; ni < 8; ni++) {
        int col = ni * 8 + (lane & 3) * 2;
        *(__half2*)&O[base + (size_t)row0 * K_D + col] =
            __floats2half2_rn(accO[ni][0] * inv0, accO[ni][1] * inv0);
        *(__half2*)&O[base + (size_t)(row0 + 8) * K_D + col] =
            __floats2half2_rn(accO[ni][2] * inv1, accO[ni][3] * inv1);
    }
}

// ---------------------------------------------------------------------------
extern "C" void kernel_launch(void* const* d_in, const int* in_sizes, int n_in,
                              void* d_out, int out_size)
{
    const float* query = (const float*)d_in[0];
    const float* key   = (const float*)d_in[1];
    const float* value = (const float*)d_in[2];
    const float* Wq    = (const float*)d_in[3];
    const float* bq    = (const float*)d_in[4];
    const float* Wk    = (const float*)d_in[5];
    const float* bk    = (const float*)d_in[6];
    const float* Wv    = (const float*)d_in[7];
    const float* bv    = (const float*)d_in[8];
    const float* Wo    = (const float*)d_in[9];
    const float* bo    = (const float*)d_in[10];
    float* out = (float*)d_out;

    __half *xq, *xk, *xv, *hwq, *hwk, *hwv, *hwo, *qh, *kh, *vh, *ch;
    cudaGetSymbolAddress((void**)&xq, g_Xq);
    cudaGetSymbolAddress((void**)&xk, g_Xk);
    cudaGetSymbolAddress((void**)&xv, g_Xv);
    cudaGetSymbolAddress((void**)&hwq, g_hWq);
    cudaGetSymbolAddress((void**)&hwk, g_hWk);
    cudaGetSymbolAddress((void**)&hwv, g_hWv);
    cudaGetSymbolAddress((void**)&hwo, g_hWo);
    cudaGetSymbolAddress((void**)&qh, g_Qh);
    cudaGetSymbolAddress((void**)&kh, g_Kh);
    cudaGetSymbolAddress((void**)&vh, g_Vh);
    cudaGetSymbolAddress((void**)&ch, g_Ch);

    static bool attr_done = false;
    if (!attr_done) {
        cudaFuncSetAttribute(gemm_tc<__half>,
                             cudaFuncAttributeMaxDynamicSharedMemorySize, 110592);
        cudaFuncSetAttribute(gemm_tc<float>,
                             cudaFuncAttributeMaxDynamicSharedMemorySize, 110592);
        cudaFuncSetAttribute(flash_tc,
                             cudaFuncAttributeMaxDynamicSharedMemorySize, 64512);
        attr_done = true;
    }

    // 1) convert inputs + weights to half
    dim3 cvt_grid(512, 7);
    cvt_all<<<cvt_grid, 256>>>(query, key, value, Wq, Wk, Wv, Wo,
                               xq, xk, xv, hwq, hwk, hwv, hwo);

    // 2) Q/K/V projections batched in ONE launch (grid.z = 3)
    dim3 gemm_grid3(K_D / 128, K_ROWS / 128, 3);   // (8, 64, 3)
    gemm_tc<__half><<<gemm_grid3, 256, 110592>>>(
        xq, xk, xv, hwq, hwk, hwv, bq, bk, bv, qh, kh, vh);

    // 3) attention (half in, half out): Br=64, 128 threads, 3 CTAs/SM
    dim3 attn_grid(K_B * K_H, K_S / 64);           // (64, 32)
    flash_tc<<<attn_grid, 128, 64512>>>(qh, kh, vh, ch);

    // 4) output projection (half in, float out)
    dim3 gemm_grid1(K_D / 128, K_ROWS / 128, 1);
    gemm_tc<float><<<gemm_grid1, 256, 110592>>>(
        ch, ch, ch, hwo, hwo, hwo, bo, bo, bo, out, out, out);
}

// round 17
// speedup vs baseline: 1.0314x; 1.0314x over previous
#include <cuda_runtime.h>
#include <cuda_fp16.h>
#include <cstdint>

#define K_B 4
#define K_S 2048
#define K_D 1024
#define K_H 16
#define K_DH 64
#define K_ROWS (K_B * K_S)   // 8192

// Half-precision scratch (device globals: allocation-free per harness rules)
__device__ __half g_Xq[K_ROWS * K_D];
__device__ __half g_Xk[K_ROWS * K_D];
__device__ __half g_Xv[K_ROWS * K_D];
__device__ __half g_hWq[K_D * K_D];
__device__ __half g_hWk[K_D * K_D];
__device__ __half g_hWv[K_D * K_D];
__device__ __half g_hWo[K_D * K_D];
__device__ __half g_Qh[K_ROWS * K_D];
__device__ __half g_Kh[K_ROWS * K_D];
__device__ __half g_Vh[K_ROWS * K_D];
__device__ __half g_Ch[K_ROWS * K_D];

// ---------------------------------------------------------------------------
// helpers
// ---------------------------------------------------------------------------
__device__ __forceinline__ unsigned h2u(__half2 h) {
    return *reinterpret_cast<unsigned*>(&h);
}

__device__ __forceinline__ float ex2f(float x) {
    float y;
    asm("ex2.approx.f32 %0, %1;" : "=f"(y) : "f"(x));
    return y;
}

// pack two f32 into f16x2 (lo = flo, hi = fhi) then exp2 both halves in one MUFU
__device__ __forceinline__ unsigned ex2_h2(float flo, float fhi) {
    unsigned r;
    asm("{\n\t.reg .b32 t;\n\t"
        "cvt.rn.f16x2.f32 t, %2, %1;\n\t"
        "ex2.approx.f16x2 %0, t;\n\t}"
        : "=r"(r) : "f"(flo), "f"(fhi));
    return r;
}

__device__ __forceinline__ void mma_f16(float* d, const uint4 a, unsigned b0, unsigned b1) {
    asm volatile(
        "mma.sync.aligned.m16n8k16.row.col.f32.f16.f16.f32 "
        "{%0,%1,%2,%3}, {%4,%5,%6,%7}, {%8,%9}, {%0,%1,%2,%3};\n"
        : "+f"(d[0]), "+f"(d[1]), "+f"(d[2]), "+f"(d[3])
        : "r"(a.x), "r"(a.y), "r"(a.z), "r"(a.w), "r"(b0), "r"(b1));
}

__device__ __forceinline__ void ldsm_x4(uint4& d, unsigned addr) {
    asm volatile("ldmatrix.sync.aligned.m8n8.x4.shared.b16 {%0,%1,%2,%3}, [%4];"
        : "=r"(d.x), "=r"(d.y), "=r"(d.z), "=r"(d.w) : "r"(addr));
}

__device__ __forceinline__ void ldsm_x4_t(uint4& d, unsigned addr) {
    asm volatile("ldmatrix.sync.aligned.m8n8.x4.trans.shared.b16 {%0,%1,%2,%3}, [%4];"
        : "=r"(d.x), "=r"(d.y), "=r"(d.z), "=r"(d.w) : "r"(addr));
}

__device__ __forceinline__ void cp16(unsigned dst, const void* src) {
    asm volatile("cp.async.cg.shared.global [%0], [%1], 16;\n" :: "r"(dst), "l"(src));
}
#define CP_COMMIT() asm volatile("cp.async.commit_group;\n" ::: "memory")
#define CP_WAIT0()  asm volatile("cp.async.wait_group 0;\n" ::: "memory")
#define CP_WAIT1()  asm volatile("cp.async.wait_group 1;\n" ::: "memory")
#define CP_WAIT2()  asm volatile("cp.async.wait_group 2;\n" ::: "memory")

#define ONES_F16X2 0x3C003C00u   // (1.0h, 1.0h)

// ---------------------------------------------------------------------------
// Conversion kernel: f32 -> f16 for 3 activations + 4 weight matrices
// ---------------------------------------------------------------------------
__global__ __launch_bounds__(256) void cvt_all(
    const float* s0, const float* s1, const float* s2, const float* s3,
    const float* s4, const float* s5, const float* s6,
    __half* d0, __half* d1, __half* d2, __half* d3,
    __half* d4, __half* d5, __half* d6)
{
    const float* ss[7] = {s0, s1, s2, s3, s4, s5, s6};
    __half* dd[7] = {d0, d1, d2, d3, d4, d5, d6};
    int t = blockIdx.y;
    int n4 = (t < 3) ? (K_ROWS * K_D / 4) : (K_D * K_D / 4);
    const float4* src = (const float4*)ss[t];
    uint2* dst = (uint2*)dd[t];
    for (int i = blockIdx.x * 256 + threadIdx.x; i < n4; i += gridDim.x * 256) {
        float4 v = src[i];
        uint2 w;
        w.x = h2u(__floats2half2_rn(v.x, v.y));
        w.y = h2u(__floats2half2_rn(v.z, v.w));
        dst[i] = w;
    }
}

// ---------------------------------------------------------------------------
// GEMM (unchanged, best measured): out = x @ W^T + bias.
// BM=BN=128, BK=64, 256 threads (8 warps), warp tile 32x64.
// 3-stage cp.async pipeline, ONE __syncthreads per 64-wide k-iter.
// Dynamic smem: 3 * (18432 A + 18432 B) = 110592 B. 2 CTAs/SM.
// ---------------------------------------------------------------------------
extern __shared__ unsigned char smem_raw[];

#define G_STRIDE 144u
#define G_TILE   18432u
#define G_STAGE  36864u

template <typename OutT>
__global__ __launch_bounds__(256, 2) void gemm_tc(
    const __half* __restrict__ x0, const __half* __restrict__ x1, const __half* __restrict__ x2,
    const __half* __restrict__ w0, const __half* __restrict__ w1, const __half* __restrict__ w2,
    const float* __restrict__ b0,  const float* __restrict__ b1,  const float* __restrict__ b2,
    OutT* __restrict__ o0, OutT* __restrict__ o1, OutT* __restrict__ o2)
{
    const int z = blockIdx.z;
    const __half* x = (z == 0) ? x0 : (z == 1) ? x1 : x2;
    const __half* W = (z == 0) ? w0 : (z == 1) ? w1 : w2;
    const float* bias = (z == 0) ? b0 : (z == 1) ? b1 : b2;
    OutT* out = (z == 0) ? o0 : (z == 1) ? o1 : o2;

    const int tid  = threadIdx.x;
    const int lane = tid & 31;
    const int warp = tid >> 5;
    const int wm = warp >> 1;
    const int wn = warp & 1;
    const int rowBase = blockIdx.y * 128;
    const int colBase = blockIdx.x * 128;

    const unsigned sb = (unsigned)__cvta_generic_to_shared(smem_raw);
    const int u = lane >> 3, j = lane & 7;
    const int a_row = wm * 32 + (u & 1) * 8 + j;
    const int a_kx  = (u >> 1) * 16;
    const int b_row = wn * 64 + (u >> 1) * 8 + j;
    const int b_kx  = (u & 1) * 16;

    auto stage = [&](int t, int s) {
        const unsigned ab = sb + (unsigned)s * G_STAGE;
        const unsigned bb = ab + G_TILE;
        const int k0 = t * 64;
        #pragma unroll
        for (int i = 0; i < 4; i++) {
            int ca = tid + i * 256;
            int r = ca >> 3, c = ca & 7;
            cp16(ab + (unsigned)(r * G_STRIDE + c * 16),
                 x + (size_t)(rowBase + r) * K_D + k0 + c * 8);
            cp16(bb + (unsigned)(r * G_STRIDE + c * 16),
                 W + (size_t)(colBase + r) * K_D + k0 + c * 8);
        }
        CP_COMMIT();
    };

    float acc[2][8][4];
    #pragma unroll
    for (int mi = 0; mi < 2; mi++)
        #pragma unroll
        for (int ni = 0; ni < 8; ni++)
            #pragma unroll
            for (int v = 0; v < 4; v++) acc[mi][ni][v] = 0.f;

    const int NT = K_D / 64;
    stage(0, 0);
    stage(1, 1);

    for (int it = 0; it < NT; it++) {
        const int buf = it % 3;
        if (it == NT - 1) { CP_WAIT0(); } else { CP_WAIT1(); }
        __syncthreads();
        if (it + 2 < NT) stage(it + 2, (it + 2) % 3);

        const unsigned ab = sb + (unsigned)buf * G_STAGE;
        const unsigned bb_ = ab + G_TILE;
        #pragma unroll
        for (int kt = 0; kt < 4; kt++) {
            uint4 afr[2];
            #pragma unroll
            for (int mi = 0; mi < 2; mi++)
                ldsm_x4(afr[mi], ab + (unsigned)((a_row + mi * 16) * G_STRIDE + kt * 32 + a_kx));
            #pragma unroll
            for (int np = 0; np < 4; np++) {
                uint4 bb;
                ldsm_x4(bb, bb_ + (unsigned)((b_row + np * 16) * G_STRIDE + kt * 32 + b_kx));
                #pragma unroll
                for (int mi = 0; mi < 2; mi++) {
                    mma_f16(acc[mi][2 * np],     afr[mi], bb.x, bb.y);
                    mma_f16(acc[mi][2 * np + 1], afr[mi], bb.z, bb.w);
                }
            }
        }
    }

    #pragma unroll
    for (int mi = 0; mi < 2; mi++) {
        int row0 = rowBase + (wm * 2 + mi) * 16 + (lane >> 2);
        #pragma unroll
        for (int ni = 0; ni < 8; ni++) {
            int col = colBase + (wn * 8 + ni) * 8 + (lane & 3) * 2;
            float bb0 = __ldg(&bias[col]);
            float bb1 = __ldg(&bias[col + 1]);
            float c00 = acc[mi][ni][0] + bb0, c01 = acc[mi][ni][1] + bb1;
            float c10 = acc[mi][ni][2] + bb0, c11 = acc[mi][ni][3] + bb1;
            if constexpr (sizeof(OutT) == 2) {
                *(__half2*)&out[(size_t)row0 * K_D + col] = __floats2half2_rn(c00, c01);
                *(__half2*)&out[(size_t)(row0 + 8) * K_D + col] = __floats2half2_rn(c10, c11);
            } else {
                *(float2*)&out[(size_t)row0 * K_D + col] = make_float2(c00, c01);
                *(float2*)&out[(size_t)(row0 + 8) * K_D + col] = make_float2(c10, c11);
            }
        }
    }
}

// ---------------------------------------------------------------------------
// Flash attention (R15 shape + Q hoisted to registers):
// Br=128, 8 warps (warp tile 16x64), Bc=64, 3-stage cp.async,
// half2-exp softmax, row-sum via MMA-with-ones, alpha-skip rescale.
// Grid: (B*H, S/128). Block: 256 threads. 2 CTAs/SM.
// Dynamic smem: Q 18432 + 3*(K 9216 + V 9216) = 73728 B.
// ---------------------------------------------------------------------------
#define FS 72   // half stride (64 data + 8 pad) => 144B rows

__global__ __launch_bounds__(256, 2) void flash_tc(
    const __half* __restrict__ Q, const __half* __restrict__ K,
    const __half* __restrict__ V, __half* __restrict__ O)
{
    const unsigned qs_base = (unsigned)__cvta_generic_to_shared(smem_raw);

    const int tid  = threadIdx.x;
    const int lane = tid & 31;
    const int warp = tid >> 5;

    const int bh = blockIdx.x;
    const int b = bh / K_H, h = bh % K_H;
    const int qbase = blockIdx.y * 128;
    const size_t base = (size_t)b * K_S * K_D + (size_t)h * K_DH;
    const float cl2 = 0.18033688f;   // (1/sqrt(64)) * log2(e)

    const int u = lane >> 3, j = lane & 7;
    const int q_row = warp * 16 + (u & 1) * 8 + j;
    const int q_kx  = (u >> 1) * 16;
    const int k_row = (u >> 1) * 8 + j;
    const int k_kx  = (u & 1) * 16;
    const int v_row = (u & 1) * 8 + j;
    const int v_dx  = (u >> 1) * 16;

    // K/V staging: 64 rows x 8 chunks = 512 chunks per tensor, 2/thread
    auto stage_kv = [&](int t, int s) {
        const unsigned kb = qs_base + 18432u + (unsigned)s * 18432u;
        const unsigned vb = kb + 9216u;
        const int r0 = t * 64;
        #pragma unroll
        for (int i = 0; i < 2; i++) {
            int ca = tid + i * 256;
            int r = ca >> 3, ch = ca & 7;
            cp16(kb + (unsigned)(r * 144 + ch * 16),
                 K + base + (size_t)(r0 + r) * K_D + ch * 8);
            cp16(vb + (unsigned)(r * 144 + ch * 16),
                 V + base + (size_t)(r0 + r) * K_D + ch * 8);
        }
        CP_COMMIT();
    };

    // prologue: Q (1024 chunks, 4/thread) as its OWN commit group, then KV 0,1
    #pragma unroll
    for (int i = 0; i < 4; i++) {
        int c = tid + i * 256;
        int r = c >> 3, ch = c & 7;
        cp16(qs_base + (unsigned)(r * 144 + ch * 16),
             Q + base + (size_t)(qbase + r) * K_D + ch * 8);
    }
    CP_COMMIT();
    stage_kv(0, 0);
    stage_kv(1, 1);

    // wait Q group only (KV 0,1 still in flight), hoist Q fragments to regs
    CP_WAIT2();
    __syncthreads();
    uint4 qf[4];
    #pragma unroll
    for (int kt = 0; kt < 4; kt++)
        ldsm_x4(qf[kt], qs_base + (unsigned)(q_row * 144 + kt * 32 + q_kx));

    float accO[8][4];
    #pragma unroll
    for (int ni = 0; ni < 8; ni++)
        #pragma unroll
        for (int v = 0; v < 4; v++) accO[ni][v] = 0.f;

    float m0 = -1e30f, m1 = -1e30f, l0 = 0.f, l1 = 0.f;

    const int NT = K_S / 64;   // 32 kv tiles

    for (int it = 0; it < NT; it++) {
        const int buf = it % 3;
        if (it == NT - 1) { CP_WAIT0(); } else { CP_WAIT1(); }
        __syncthreads();
        if (it + 2 < NT) stage_kv(it + 2, (it + 2) % 3);

        const unsigned ks = qs_base + 18432u + (unsigned)buf * 18432u;
        const unsigned vs = ks + 9216u;

        // ---- S = Q K^T : warp tile 16q x 64kv (Q from registers) ----
        float accS[8][4];
        #pragma unroll
        for (int ni = 0; ni < 8; ni++)
            #pragma unroll
            for (int v = 0; v < 4; v++) accS[ni][v] = 0.f;

        #pragma unroll
        for (int kt = 0; kt < 4; kt++) {
            #pragma unroll
            for (int np = 0; np < 4; np++) {
                uint4 bb;
                ldsm_x4(bb, ks + (unsigned)((k_row + np * 16) * 144 + kt * 32 + k_kx));
                mma_f16(accS[2 * np],     qf[kt], bb.x, bb.y);
                mma_f16(accS[2 * np + 1], qf[kt], bb.z, bb.w);
            }
        }

        // ---- online softmax in exp2 domain (rows lane>>2, +8; quad-local) ----
        float mx0 = -1e30f, mx1 = -1e30f;
        #pragma unroll
        for (int ni = 0; ni < 8; ni++) {
            mx0 = fmaxf(mx0, fmaxf(accS[ni][0], accS[ni][1]));
            mx1 = fmaxf(mx1, fmaxf(accS[ni][2], accS[ni][3]));
        }
        mx0 = fmaxf(mx0, __shfl_xor_sync(0xffffffffu, mx0, 1));
        mx0 = fmaxf(mx0, __shfl_xor_sync(0xffffffffu, mx0, 2));
        mx1 = fmaxf(mx1, __shfl_xor_sync(0xffffffffu, mx1, 1));
        mx1 = fmaxf(mx1, __shfl_xor_sync(0xffffffffu, mx1, 2));

        float mn0 = fmaxf(m0, mx0);
        float mn1 = fmaxf(m1, mx1);
        bool need = (mn0 > m0) || (mn1 > m1);
        if (__any_sync(0xffffffffu, need)) {
            float alpha0 = ex2f((m0 - mn0) * cl2);
            float alpha1 = ex2f((m1 - mn1) * cl2);
            #pragma unroll
            for (int ni = 0; ni < 8; ni++) {
                accO[ni][0] *= alpha0; accO[ni][1] *= alpha0;
                accO[ni][2] *= alpha1; accO[ni][3] *= alpha1;
            }
            l0 *= alpha0;
            l1 *= alpha1;
            m0 = mn0; m1 = mn1;
        }
        float mc0 = m0 * cl2, mc1 = m1 * cl2;

        unsigned uP[8][2];
        #pragma unroll
        for (int ni = 0; ni < 8; ni++) {
            uP[ni][0] = ex2_h2(fmaf(accS[ni][0], cl2, -mc0),
                               fmaf(accS[ni][1], cl2, -mc0));
            uP[ni][1] = ex2_h2(fmaf(accS[ni][2], cl2, -mc1),
                               fmaf(accS[ni][3], cl2, -mc1));
        }

        // ---- O += P @ V, plus row-sum via MMA with ones ----
        float accL[4] = {0.f, 0.f, 0.f, 0.f};
        #pragma unroll
        for (int kt = 0; kt < 4; kt++) {
            uint4 aP;
            aP.x = uP[2 * kt][0];
            aP.y = uP[2 * kt][1];
            aP.z = uP[2 * kt + 1][0];
            aP.w = uP[2 * kt + 1][1];
            mma_f16(accL, aP, ONES_F16X2, ONES_F16X2);
            #pragma unroll
            for (int np = 0; np < 4; np++) {
                uint4 bb;
                ldsm_x4_t(bb, vs + (unsigned)((kt * 16 + v_row) * 144 + np * 32 + v_dx));
                mma_f16(accO[2 * np],     aP, bb.x, bb.y);
                mma_f16(accO[2 * np + 1], aP, bb.z, bb.w);
            }
        }
        l0 += accL[0];
        l1 += accL[2];
    }

    // Epilogue: normalize and write half context
    float inv0 = 1.0f / l0;
    float inv1 = 1.0f / l1;
    int row0 = qbase + warp * 16 + (lane >> 2);
    #pragma unroll
    for (int ni = 0; ni < 8; ni++) {
        int col = ni * 8 + (lane & 3) * 2;
        *(__half2*)&O[base + (size_t)row0 * K_D + col] =
            __floats2half2_rn(accO[ni][0] * inv0, accO[ni][1] * inv0);
        *(__half2*)&O[base + (size_t)(row0 + 8) * K_D + col] =
            __floats2half2_rn(accO[ni][2] * inv1, accO[ni][3] * inv1);
    }
}

// ---------------------------------------------------------------------------
extern "C" void kernel_launch(void* const* d_in, const int* in_sizes, int n_in,
                              void* d_out, int out_size)
{
    const float* query = (const float*)d_in[0];
    const float* key   = (const float*)d_in[1];
    const float* value = (const float*)d_in[2];
    const float* Wq    = (const float*)d_in[3];
    const float* bq    = (const float*)d_in[4];
    const float* Wk    = (const float*)d_in[5];
    const float* bk    = (const float*)d_in[6];
    const float* Wv    = (const float*)d_in[7];
    const float* bv    = (const float*)d_in[8];
    const float* Wo    = (const float*)d_in[9];
    const float* bo    = (const float*)d_in[10];
    float* out = (float*)d_out;

    __half *xq, *xk, *xv, *hwq, *hwk, *hwv, *hwo, *qh, *kh, *vh, *ch;
    cudaGetSymbolAddress((void**)&xq, g_Xq);
    cudaGetSymbolAddress((void**)&xk, g_Xk);
    cudaGetSymbolAddress((void**)&xv, g_Xv);
    cudaGetSymbolAddress((void**)&hwq, g_hWq);
    cudaGetSymbolAddress((void**)&hwk, g_hWk);
    cudaGetSymbolAddress((void**)&hwv, g_hWv);
    cudaGetSymbolAddress((void**)&hwo, g_hWo);
    cudaGetSymbolAddress((void**)&qh, g_Qh);
    cudaGetSymbolAddress((void**)&kh, g_Kh);
    cudaGetSymbolAddress((void**)&vh, g_Vh);
    cudaGetSymbolAddress((void**)&ch, g_Ch);

    static bool attr_done = false;
    if (!attr_done) {
        cudaFuncSetAttribute(gemm_tc<__half>,
                             cudaFuncAttributeMaxDynamicSharedMemorySize, 110592);
        cudaFuncSetAttribute(gemm_tc<float>,
                             cudaFuncAttributeMaxDynamicSharedMemorySize, 110592);
        cudaFuncSetAttribute(flash_tc,
                             cudaFuncAttributeMaxDynamicSharedMemorySize, 73728);
        attr_done = true;
    }

    // 1) convert inputs + weights to half
    dim3 cvt_grid(512, 7);
    cvt_all<<<cvt_grid, 256>>>(query, key, value, Wq, Wk, Wv, Wo,
                               xq, xk, xv, hwq, hwk, hwv, hwo);

    // 2) Q/K/V projections batched in ONE launch (grid.z = 3)
    dim3 gemm_grid3(K_D / 128, K_ROWS / 128, 3);   // (8, 64, 3)
    gemm_tc<__half><<<gemm_grid3, 256, 110592>>>(
        xq, xk, xv, hwq, hwk, hwv, bq, bk, bv, qh, kh, vh);

    // 3) attention (half in, half out)
    dim3 attn_grid(K_B * K_H, K_S / 128);          // (64, 16)
    flash_tc<<<attn_grid, 256, 73728>>>(qh, kh, vh, ch);

    // 4) output projection (half in, float out)
    dim3 gemm_grid1(K_D / 128, K_ROWS / 128, 1);
    gemm_tc<float><<<gemm_grid1, 256, 110592>>>(
        ch, ch, ch, hwo, hwo, hwo, bo, bo, bo, out, out, out);
}